// round 16
// baseline (speedup 1.0000x reference)
#include <cuda_runtime.h>
#include <math.h>

// IDM_43748536877069  — B=8, NV=2048 pairwise IDM leader search + epilogue.
//
// Rotated-frame cone test (exact equivalence):
//   u = dx*cos(psi_j) + dy*sin(psi_j)    (longitudinal)
//   w = -dx*sin(psi_j) + dy*cos(psi_j)   (lateral)
//   cone ⟺ |w|*cot(20°) < u             (implies u>0; dx=dy=0 -> false)
// dx,dy computed explicitly so the self-pair is exactly (0,0) -> never leader.
//
// R16: R4 shape, but the running-min update is an FMNMX chain
// (best = fminf(best, cone ? u : INF)) instead of FSETP->SEL, cutting the
// loop-carried dependency from ~17 cyc to 4 cyc per candidate. The index
// update (bi = changed ? i : bi) hangs off the chain without extending it.

#define NV 2048
#define SLOTS 112                      // egos per block
#define SUBS 8                         // candidate-split per ego
#define THREADS (SLOTS * SUBS)         // 896
#define PAIRS (NV / 2)                 // 1024 float4-packed candidate pairs
#define PCHUNK (PAIRS / SUBS)          // 128 pairs per thread
#define BPB ((NV + SLOTS - 1) / SLOTS) // 19 blocks per batch

__global__ __launch_bounds__(THREADS, 1)
void idm_kernel(const float* __restrict__ state,
                const float* __restrict__ lengths,
                const float* __restrict__ v0p,
                const float* __restrict__ s0p,
                const float* __restrict__ dthp,
                const float* __restrict__ amaxp,
                const float* __restrict__ bp,
                float* __restrict__ out)
{
    __shared__ float4 xy4[PAIRS];            // 16 KB: (x0,y0,x1,y1) per pair
    __shared__ float  pval[SUBS][SLOTS];     // 3.5 KB
    __shared__ int    pidx[SUBS][SLOTS];     // 3.5 KB

    const int b       = blockIdx.x / BPB;
    const int egoBase = (blockIdx.x % BPB) * SLOTS;
    const float* st   = state + (size_t)b * NV * 5;

    // Stage candidate positions, packed two per float4.
    for (int p = threadIdx.x; p < PAIRS; p += THREADS) {
        const float* a = st + (2 * p) * 5;
        xy4[p] = make_float4(a[0], a[1], a[5], a[6]);
    }
    __syncthreads();

    // lane mapping: sub = tid&7, ego slot e = tid>>3.
    const int sub = threadIdx.x & 7;
    const int e   = threadIdx.x >> 3;
    const int j   = egoBase + e;
    const bool valid = (j < NV);
    const int jc  = valid ? j : 0;

    const float4 cj0 = xy4[jc >> 1];
    const float xj = (jc & 1) ? cj0.z : cj0.x;
    const float yj = (jc & 1) ? cj0.w : cj0.y;
    const float psj = __ldg(st + jc * 5 + 3);
    float sj, cjv;
    sincosf(psj, &sj, &cjv);

    const float COT20 = 2.7474774194546225f;   // 1/tan(20 deg)
    const float scj = cjv * COT20;
    const float nsj = -sj * COT20;

    const float INF = __int_as_float(0x7f800000);
    float best = INF;
    int   bi   = 0;

    if (valid) {
        #pragma unroll 8
        for (int t = 0; t < PCHUNK; ++t) {
            const int p = (t << 3) + sub;        // pair index, p ≡ sub (mod 8)
            const float4 c = xy4[p];

            // even candidate (i = 2p)
            const float dx0 = c.x - xj;
            const float dy0 = c.y - yj;
            const float u0  = fmaf(dx0, cjv, dy0 * sj);
            const float w0  = fmaf(dy0, scj, dx0 * nsj);
            // odd candidate (i = 2p+1)
            const float dx1 = c.z - xj;
            const float dy1 = c.w - yj;
            const float u1  = fmaf(dx1, cjv, dy1 * sj);
            const float w1  = fmaf(dy1, scj, dx1 * nsj);

            // FMNMX min-chain: loop-carried dep is a single 4-cyc FMNMX.
            const float cand0 = (fabsf(w0) < u0) ? u0 : INF;
            const float nb0   = fminf(best, cand0);
            bi   = (nb0 < best) ? (p << 1) : bi;       // strict <: first index kept
            best = nb0;

            const float cand1 = (fabsf(w1) < u1) ? u1 : INF;
            const float nb1   = fminf(best, cand1);
            bi   = (nb1 < best) ? ((p << 1) | 1) : bi;
            best = nb1;
        }
    }
    pval[sub][e] = best;
    pidx[sub][e] = bi;
    __syncthreads();

    // One thread per ego: 8-way combine (tie -> lower index) + IDM epilogue.
    if (threadIdx.x < SLOTS) {
        const int ee = threadIdx.x;
        const int jj = egoBase + ee;
        if (jj < NV) {
            float fbv = pval[0][ee];
            int   fbx = pidx[0][ee];
            #pragma unroll
            for (int s = 1; s < SUBS; ++s) {
                const float v2 = pval[s][ee];
                const int   i2 = pidx[s][ee];
                if (v2 < fbv || (v2 == fbv && i2 < fbx)) { fbv = v2; fbx = i2; }
            }

            const float v0   = v0p[0];
            const float s0   = s0p[0];
            const float dth  = dthp[0];
            const float amax = amaxp[0];
            const float bb   = bp[0];

            const float vje  = __ldg(st + jj * 5 + 2);
            const float psje = __ldg(st + jj * 5 + 3);
            float sje, cje;
            sincosf(psje, &sje, &cje);

            const float q  = vje / v0;
            const float q2 = q * q;
            const float afree = amax * (1.0f - q2 * q2);

            float action = afree;
            const float sal = fbv - lengths[jj];
            if (isfinite(sal)) {
                const float vl  = __ldg(st + fbx * 5 + 2);
                const float psl = __ldg(st + fbx * 5 + 3);
                float sl, cl;
                sincosf(psl, &sl, &cl);
                const float dvx = vl * cl - vje * cje;
                const float dvy = vl * sl - vje * sje;
                const float ndv = fmaf(dvx, cje, dvy * sje);

                const float sstar = s0 + vje * dth
                                  + vje * ndv / (2.0f * sqrtf(amax * bb));
                const float r = sstar / sal;
                action = afree - amax * r * r;
            }
            out[(size_t)b * NV + jj] = action;
        }
    }
}

extern "C" void kernel_launch(void* const* d_in, const int* in_sizes, int n_in,
                              void* d_out, int out_size) {
    const float* state   = (const float*)d_in[0];
    const float* lengths = (const float*)d_in[1];
    const float* v0      = (const float*)d_in[2];
    const float* s0      = (const float*)d_in[3];
    const float* dth     = (const float*)d_in[4];
    const float* amax    = (const float*)d_in[5];
    const float* bpar    = (const float*)d_in[6];
    float* out = (float*)d_out;

    const int B = in_sizes[0] / (NV * 5);
    const int grid = B * BPB;    // 8 * 19 = 152 == #SMs on GB300
    idm_kernel<<<grid, THREADS>>>(state, lengths, v0, s0, dth, amax, bpar, out);
}

// round 17
// speedup vs baseline: 1.1214x; 1.1214x over previous
#include <cuda_runtime.h>
#include <math.h>

// IDM_43748536877069  — B=8, NV=2048 pairwise IDM leader search + epilogue.
//
// FINAL (R17 = R4, best measured: 16.86us bench / 17.2us ncu).
//
// Rotated-frame cone test (exact equivalence with the reference):
//   u = dx*cos(psi_j) + dy*sin(psi_j)    (longitudinal distance)
//   w = -dx*sin(psi_j) + dy*cos(psi_j)   (lateral distance)
//   cone ⟺ |w|*cot(20°) < u             (implies u>0; dx=dy=0 -> false)
// dx,dy computed explicitly so the self-pair is exactly (0,0) and is never
// selected as leader (required: folded-constant forms fail correctness).
//
// Shape: 152 blocks (1/SM) x 896 threads (28 warps), 112 egos/block,
// 8 candidate-subsets/ego, candidates staged as float4 pairs in smem
// (LDS.128 = 2 candidates, warp-conflict-free broadcast).
// Evidence from 16 tuning rounds: kernel is issue-port bound at the
// exactness-preserving instruction floor (~24 issues per candidate pair);
// neither fma nor alu pipe saturates; DRAM 0.2%.

#define NV 2048
#define SLOTS 112                      // egos per block
#define SUBS 8                         // candidate-split per ego
#define THREADS (SLOTS * SUBS)         // 896
#define PAIRS (NV / 2)                 // 1024 float4-packed candidate pairs
#define PCHUNK (PAIRS / SUBS)          // 128 pairs per thread
#define BPB ((NV + SLOTS - 1) / SLOTS) // 19 blocks per batch

__global__ __launch_bounds__(THREADS, 1)
void idm_kernel(const float* __restrict__ state,
                const float* __restrict__ lengths,
                const float* __restrict__ v0p,
                const float* __restrict__ s0p,
                const float* __restrict__ dthp,
                const float* __restrict__ amaxp,
                const float* __restrict__ bp,
                float* __restrict__ out)
{
    __shared__ float4 xy4[PAIRS];            // 16 KB: (x0,y0,x1,y1) per pair
    __shared__ float  pval[SUBS][SLOTS];     // 3.5 KB
    __shared__ int    pidx[SUBS][SLOTS];     // 3.5 KB

    const int b       = blockIdx.x / BPB;
    const int egoBase = (blockIdx.x % BPB) * SLOTS;
    const float* st   = state + (size_t)b * NV * 5;

    // Stage candidate positions, packed two per float4.
    for (int p = threadIdx.x; p < PAIRS; p += THREADS) {
        const float* a = st + (2 * p) * 5;
        xy4[p] = make_float4(a[0], a[1], a[5], a[6]);
    }
    __syncthreads();

    // lane mapping: sub = tid&7, ego slot e = tid>>3.
    // A warp = 4 egos x 8 subs; loop loads xy4[8t+sub] -> 8 consecutive
    // float4 smem addresses per warp (128B, conflict-free, 4-lane broadcast).
    const int sub = threadIdx.x & 7;
    const int e   = threadIdx.x >> 3;
    const int j   = egoBase + e;
    const bool valid = (j < NV);
    const int jc  = valid ? j : 0;

    const float4 cj0 = xy4[jc >> 1];
    const float xj = (jc & 1) ? cj0.z : cj0.x;
    const float yj = (jc & 1) ? cj0.w : cj0.y;
    const float psj = __ldg(st + jc * 5 + 3);
    float sj, cjv;
    sincosf(psj, &sj, &cjv);

    const float COT20 = 2.7474774194546225f;   // 1/tan(20 deg)
    const float scj = cjv * COT20;
    const float nsj = -sj * COT20;

    float best = __int_as_float(0x7f800000);   // +inf
    int   bi   = 0;

    if (valid) {
        #pragma unroll 4
        for (int t = 0; t < PCHUNK; ++t) {
            const int p = (t << 3) + sub;        // pair index, p ≡ sub (mod 8)
            const float4 c = xy4[p];

            // even candidate (i = 2p)
            const float dx0 = c.x - xj;
            const float dy0 = c.y - yj;
            const float u0  = fmaf(dx0, cjv, dy0 * sj);
            const float w0  = fmaf(dy0, scj, dx0 * nsj);
            // odd candidate (i = 2p+1)
            const float dx1 = c.z - xj;
            const float dy1 = c.w - yj;
            const float u1  = fmaf(dx1, cjv, dy1 * sj);
            const float w1  = fmaf(dy1, scj, dx1 * nsj);

            const bool ok0 = (fabsf(w0) < u0) && (u0 < best);
            best = ok0 ? u0 : best;
            bi   = ok0 ? (p << 1) : bi;
            const bool ok1 = (fabsf(w1) < u1) && (u1 < best);
            best = ok1 ? u1 : best;
            bi   = ok1 ? ((p << 1) | 1) : bi;
        }
    }
    pval[sub][e] = best;
    pidx[sub][e] = bi;
    __syncthreads();

    // One thread per ego: 8-way combine (tie -> lower index) + IDM epilogue.
    if (threadIdx.x < SLOTS) {
        const int ee = threadIdx.x;
        const int jj = egoBase + ee;
        if (jj < NV) {
            float fbv = pval[0][ee];
            int   fbx = pidx[0][ee];
            #pragma unroll
            for (int s = 1; s < SUBS; ++s) {
                const float v2 = pval[s][ee];
                const int   i2 = pidx[s][ee];
                if (v2 < fbv || (v2 == fbv && i2 < fbx)) { fbv = v2; fbx = i2; }
            }

            const float v0   = v0p[0];
            const float s0   = s0p[0];
            const float dth  = dthp[0];
            const float amax = amaxp[0];
            const float bb   = bp[0];

            const float vje  = __ldg(st + jj * 5 + 2);
            const float psje = __ldg(st + jj * 5 + 3);
            float sje, cje;
            sincosf(psje, &sje, &cje);

            const float q  = vje / v0;
            const float q2 = q * q;
            const float afree = amax * (1.0f - q2 * q2);

            float action = afree;
            const float sal = fbv - lengths[jj];
            if (isfinite(sal)) {
                const float vl  = __ldg(st + fbx * 5 + 2);
                const float psl = __ldg(st + fbx * 5 + 3);
                float sl, cl;
                sincosf(psl, &sl, &cl);
                const float dvx = vl * cl - vje * cje;
                const float dvy = vl * sl - vje * sje;
                const float ndv = fmaf(dvx, cje, dvy * sje);

                const float sstar = s0 + vje * dth
                                  + vje * ndv / (2.0f * sqrtf(amax * bb));
                const float r = sstar / sal;
                action = afree - amax * r * r;
            }
            out[(size_t)b * NV + jj] = action;
        }
    }
}

extern "C" void kernel_launch(void* const* d_in, const int* in_sizes, int n_in,
                              void* d_out, int out_size) {
    const float* state   = (const float*)d_in[0];
    const float* lengths = (const float*)d_in[1];
    const float* v0      = (const float*)d_in[2];
    const float* s0      = (const float*)d_in[3];
    const float* dth     = (const float*)d_in[4];
    const float* amax    = (const float*)d_in[5];
    const float* bpar    = (const float*)d_in[6];
    float* out = (float*)d_out;

    const int B = in_sizes[0] / (NV * 5);
    const int grid = B * BPB;    // 8 * 19 = 152 == #SMs on GB300
    idm_kernel<<<grid, THREADS>>>(state, lengths, v0, s0, dth, amax, bpar, out);
}